// round 1
// baseline (speedup 1.0000x reference)
#include <cuda_runtime.h>
#include <math.h>

#define BATCH 64
#define SEQ   1024
#define ISZ   256
#define HSZ   512
#define GSZ   2048   /* 4*HSZ */
#define CON   768    /* ISZ+HSZ */
#define OSZ   256
#define NCTA  128
#define TPB   128

// ---------------- device scratch (static globals: allocation-free) ----------
__device__ float    g_xg[(size_t)SEQ * BATCH * GSZ];   // 512 MB: x@Wx + bias, per step
__device__ float    g_Wall[CON * GSZ];                 // repacked [768,2048]
__device__ float    g_ball[GSZ];
__device__ float    g_h[2][BATCH * HSZ];               // ping-pong hidden state
__device__ unsigned g_bar_count = 0;
__device__ unsigned g_bar_gen   = 0;

// ---------------- prep: repack weights, zero h ------------------------------
__global__ void prep_kernel(const float* __restrict__ Wf, const float* __restrict__ Wi,
                            const float* __restrict__ Wc, const float* __restrict__ Wo,
                            const float* __restrict__ bf, const float* __restrict__ bi,
                            const float* __restrict__ bc, const float* __restrict__ bo) {
    int idx = blockIdx.x * blockDim.x + threadIdx.x;
    int stride = gridDim.x * blockDim.x;
    for (int i = idx; i < CON * GSZ; i += stride) {
        int k = i >> 11; int n = i & (GSZ - 1);
        int g = n >> 9;  int j = n & (HSZ - 1);
        const float* W = (g == 0) ? Wf : (g == 1) ? Wi : (g == 2) ? Wc : Wo;
        g_Wall[i] = W[k * HSZ + j];
    }
    for (int i = idx; i < GSZ; i += stride) {
        int g = i >> 9; int j = i & (HSZ - 1);
        const float* bp = (g == 0) ? bf : (g == 1) ? bi : (g == 2) ? bc : bo;
        g_ball[i] = bp[j];
    }
    for (int i = idx; i < 2 * BATCH * HSZ; i += stride)
        ((float*)g_h)[i] = 0.f;
}

// ---------------- precompute xg = x @ Wx + b_all ----------------------------
// grid (16, 1024): blockIdx.x = n-tile (128 cols), blockIdx.y = timestep.
// CTA tile 64x128, K=256 in 16 chunks of 16; 256 thr, 4x8 micro-tile.
__global__ void __launch_bounds__(256) xgemm_kernel(const float* __restrict__ x) {
    __shared__ float As[16 * 68];    // [k][m] pad 68
    __shared__ float Bs[16 * 132];   // [k][n] pad 132
    int tid  = threadIdx.x;
    int n0   = blockIdx.x * 128;
    int tt   = blockIdx.y;
    int rowg = tid >> 4;             // 0..15 -> rows rowg*4..+3
    int colg = tid & 15;             // 0..15 -> cols colg*8..+7

    float acc[4][8];
    #pragma unroll
    for (int cc = 0; cc < 8; cc++) {
        float b = g_ball[n0 + colg * 8 + cc];
        acc[0][cc] = b; acc[1][cc] = b; acc[2][cc] = b; acc[3][cc] = b;
    }

    int ar = tid >> 2, akq = tid & 3;
    const float* aptr = x + ((size_t)ar * SEQ + tt) * ISZ + akq * 4;

    #pragma unroll 1
    for (int ch = 0; ch < 16; ch++) {
        float4 av = *(const float4*)(aptr + ch * 16);
        float4 bv0, bv1;
        {
            int f = tid;       int bk = f >> 5, j4 = f & 31;
            bv0 = *(const float4*)&g_Wall[(ch * 16 + bk) * GSZ + n0 + j4 * 4];
            f = 256 + tid;     bk = f >> 5;     j4 = f & 31;
            bv1 = *(const float4*)&g_Wall[(ch * 16 + bk) * GSZ + n0 + j4 * 4];
        }
        __syncthreads();
        As[(akq * 4 + 0) * 68 + ar] = av.x;
        As[(akq * 4 + 1) * 68 + ar] = av.y;
        As[(akq * 4 + 2) * 68 + ar] = av.z;
        As[(akq * 4 + 3) * 68 + ar] = av.w;
        {
            int f = tid;       int bk = f >> 5, j4 = f & 31;
            *(float4*)&Bs[bk * 132 + j4 * 4] = bv0;
            f = 256 + tid;     bk = f >> 5;     j4 = f & 31;
            *(float4*)&Bs[bk * 132 + j4 * 4] = bv1;
        }
        __syncthreads();
        #pragma unroll
        for (int k = 0; k < 16; k++) {
            float4 a4  = *(const float4*)&As[k * 68 + rowg * 4];
            float4 b40 = *(const float4*)&Bs[k * 132 + colg * 8];
            float4 b41 = *(const float4*)&Bs[k * 132 + colg * 8 + 4];
            float a[4]  = {a4.x, a4.y, a4.z, a4.w};
            float bb[8] = {b40.x, b40.y, b40.z, b40.w, b41.x, b41.y, b41.z, b41.w};
            #pragma unroll
            for (int rr = 0; rr < 4; rr++)
                #pragma unroll
                for (int cc = 0; cc < 8; cc++)
                    acc[rr][cc] += a[rr] * bb[cc];
        }
    }
    #pragma unroll
    for (int rr = 0; rr < 4; rr++) {
        size_t base = ((size_t)(tt * BATCH + rowg * 4 + rr)) * GSZ + n0 + colg * 8;
        *(float4*)&g_xg[base]     = make_float4(acc[rr][0], acc[rr][1], acc[rr][2], acc[rr][3]);
        *(float4*)&g_xg[base + 4] = make_float4(acc[rr][4], acc[rr][5], acc[rr][6], acc[rr][7]);
    }
}

// ---------------- persistent recurrent kernel -------------------------------
// 128 CTAs (one/SM, co-resident), 128 thr. CTA ct owns hidden cols j0..j0+3
// -> 16 gate cols [f0..3|i0..3|u0..3|o0..3]. W slice resident in smem.
__global__ void __launch_bounds__(TPB, 1) lstm_kernel() {
    extern __shared__ float sm[];
    float* Ws = sm;            // 512*16            = 8192
    float* Hs = sm + 8192;     // [k][b] 64*68      = 4352
    float* Gs = sm + 12544;    // 64*16             = 1024
    float* Cs = sm + 13568;    // 64*4              = 256
    float* Ho = sm + 13824;    // 64*4              = 256  (total 14080 fl = 56320 B)

    int tid = threadIdx.x;
    int ct  = blockIdx.x;
    int j0  = ct * 4;

    // load resident W_h slice: Ws[k*16 + c], c = gate*4 + jj
    for (int i = tid; i < HSZ * 16; i += TPB) {
        int k = i >> 4, c = i & 15, g = c >> 2, jj = c & 3;
        Ws[i] = g_Wall[(ISZ + k) * GSZ + g * HSZ + j0 + jj];
    }
    for (int i = tid; i < 256; i += TPB) Cs[i] = 0.f;

    int rowg = tid >> 3;        // 0..15 -> rows rowg*4..+3
    int colg = tid & 7;         // 0..7  -> cols colg*2, colg*2+1
    int kl   = tid & 63;        // staging: k within chunk
    int bh   = (tid >> 6) * 32; // staging: b half
    __syncthreads();

    #pragma unroll 1
    for (int t = 0; t < SEQ; t++) {
        int rb = t & 1, wb = rb ^ 1;
        const float* hsrc = g_h[rb];

        // prefetch this thread's xg gate inputs (independent of h)
        float xgv[2][4];
        #pragma unroll
        for (int s = 0; s < 2; s++) {
            int p = tid * 2 + s; int b = p >> 2; int jj = p & 3;
            size_t xb = ((size_t)(t * BATCH + b)) * GSZ + j0 + jj;
            xgv[s][0] = g_xg[xb];
            xgv[s][1] = g_xg[xb + 512];
            xgv[s][2] = g_xg[xb + 1024];
            xgv[s][3] = g_xg[xb + 1536];
        }

        float acc[4][2] = {};
        // prefetch chunk 0 of h into regs (transpose gather, coalesced)
        float st[8][4];
        #pragma unroll
        for (int q = 0; q < 8; q++) {
            int b0 = bh + q * 4;
            #pragma unroll
            for (int i2 = 0; i2 < 4; i2++)
                st[q][i2] = __ldcg(&hsrc[(b0 + i2) * HSZ + kl]);
        }

        #pragma unroll 1
        for (int ch = 0; ch < 8; ch++) {
            __syncthreads();   // prior chunk's compute done
            #pragma unroll
            for (int q = 0; q < 8; q++) {
                int b0 = bh + q * 4;
                *(float4*)&Hs[kl * 68 + b0] =
                    make_float4(st[q][0], st[q][1], st[q][2], st[q][3]);
            }
            __syncthreads();
            if (ch < 7) {
                #pragma unroll
                for (int q = 0; q < 8; q++) {
                    int b0 = bh + q * 4;
                    #pragma unroll
                    for (int i2 = 0; i2 < 4; i2++)
                        st[q][i2] = __ldcg(&hsrc[(b0 + i2) * HSZ + (ch + 1) * 64 + kl]);
                }
            }
            const float* wp = Ws + ch * 64 * 16 + colg * 2;
            #pragma unroll
            for (int k = 0; k < 64; k++) {
                float4 hv = *(const float4*)&Hs[k * 68 + rowg * 4];
                float2 wv = *(const float2*)(wp + k * 16);
                acc[0][0] += hv.x * wv.x; acc[0][1] += hv.x * wv.y;
                acc[1][0] += hv.y * wv.x; acc[1][1] += hv.y * wv.y;
                acc[2][0] += hv.z * wv.x; acc[2][1] += hv.z * wv.y;
                acc[3][0] += hv.w * wv.x; acc[3][1] += hv.w * wv.y;
            }
        }

        // gates + state update
        #pragma unroll
        for (int rr = 0; rr < 4; rr++) {
            Gs[(rowg * 4 + rr) * 16 + colg * 2]     = acc[rr][0];
            Gs[(rowg * 4 + rr) * 16 + colg * 2 + 1] = acc[rr][1];
        }
        __syncthreads();
        #pragma unroll
        for (int s = 0; s < 2; s++) {
            int p = tid * 2 + s; int b = p >> 2; int jj = p & 3;
            float gf = Gs[b * 16 + jj]      + xgv[s][0];
            float gi = Gs[b * 16 + 4 + jj]  + xgv[s][1];
            float gu = Gs[b * 16 + 8 + jj]  + xgv[s][2];
            float go = Gs[b * 16 + 12 + jj] + xgv[s][3];
            float fg = 1.f / (1.f + expf(-gf));
            float ig = 1.f / (1.f + expf(-gi));
            float ug = tanhf(gu);
            float og = 1.f / (1.f + expf(-go));
            float cn = fg * Cs[p] + ig * ug;
            Cs[p] = cn;
            Ho[p] = og * tanhf(cn);
        }
        __syncthreads();
        if (tid < BATCH)
            *(float4*)&g_h[wb][tid * HSZ + j0] = *(const float4*)&Ho[tid * 4];

        // grid barrier (sense via monotonic generation: graph-replay safe)
        __threadfence();
        __syncthreads();
        if (tid == 0) {
            unsigned gen = *(volatile unsigned*)&g_bar_gen;
            unsigned ticket = atomicAdd(&g_bar_count, 1u);
            if (ticket == NCTA - 1) {
                g_bar_count = 0;
                __threadfence();
                atomicAdd(&g_bar_gen, 1u);
            } else {
                while (*(volatile unsigned*)&g_bar_gen == gen) { }
            }
            __threadfence();
        }
        __syncthreads();
    }
}

// ---------------- final projection out = h_final @ W_out + b_out ------------
__global__ void __launch_bounds__(256) out_kernel(const float* __restrict__ Wout,
                                                  const float* __restrict__ bout,
                                                  float* __restrict__ out) {
    __shared__ float hs[HSZ];
    int b = blockIdx.x, n = threadIdx.x;
    for (int i = n; i < HSZ; i += 256) hs[i] = g_h[0][b * HSZ + i];
    __syncthreads();
    float acc = bout[n];
    #pragma unroll 8
    for (int k = 0; k < HSZ; k++) acc += hs[k] * Wout[k * OSZ + n];
    out[b * OSZ + n] = acc;
}

// ---------------- launch -----------------------------------------------------
extern "C" void kernel_launch(void* const* d_in, const int* in_sizes, int n_in,
                              void* d_out, int out_size) {
    const float* x    = (const float*)d_in[0];
    const float* Wf   = (const float*)d_in[1];
    const float* bf   = (const float*)d_in[2];
    const float* Wi   = (const float*)d_in[3];
    const float* bi   = (const float*)d_in[4];
    const float* Wc   = (const float*)d_in[5];
    const float* bc   = (const float*)d_in[6];
    const float* Wo   = (const float*)d_in[7];
    const float* bo   = (const float*)d_in[8];
    const float* Wout = (const float*)d_in[9];
    const float* bout = (const float*)d_in[10];
    float* out = (float*)d_out;

    cudaFuncSetAttribute(lstm_kernel, cudaFuncAttributeMaxDynamicSharedMemorySize, 57344);

    prep_kernel<<<512, 256>>>(Wf, Wi, Wc, Wo, bf, bi, bc, bo);
    dim3 g(16, SEQ);
    xgemm_kernel<<<g, 256>>>(x);
    lstm_kernel<<<NCTA, TPB, 56320>>>();
    out_kernel<<<BATCH, 256>>>(Wout, bout, out);
}